// round 1
// baseline (speedup 1.0000x reference)
#include <cuda_runtime.h>
#include <cstdint>

// Problem constants (fixed shapes from reference)
#define NWORDS  16384      // B*NW = 64*256
#define LW      32         // chars per word
#define NC      64         // char vocab
#define E3      256        // per-slot embedding dim
#define OUTW    770        // output width (2 pad + 3*256)
#define WT_S    257        // padded shared stride for WT (conflict-free)
#define NGROUPS 2048       // NWORDS / 8 (8 words processed per block iteration)
#define NBLK    444        // persistent grid: 148 SMs * 3 blocks
#define BLOCKT  256

static constexpr int SMEM_BYTES = NC * WT_S * 4 + 8 * 32;  // WT + packed chars

__global__ __launch_bounds__(BLOCKT) void opb_kernel(
    const int* __restrict__ sntcs, const float* __restrict__ W,
    float* __restrict__ out)
{
    extern __shared__ float smem[];
    float* sWT = smem;                                           // [64][257] floats
    unsigned char* sChars = reinterpret_cast<unsigned char*>(smem + NC * WT_S);  // [8][32] bytes

    const int tid  = threadIdx.x;
    const int lane = tid & 31;
    const int wj   = tid >> 5;          // warp id = word-within-group

    // ---- Fill shared WT: WT[c][e] = W[e*64 + c]  (once per block) ----
    // Warp reads W coalesced; writes hit banks (c + e) % 32 -> conflict-free.
    for (int idx = tid; idx < E3 * NC; idx += BLOCKT) {
        int e = idx >> 6, c = idx & 63;
        sWT[c * WT_S + e] = W[idx];
    }

    int g = blockIdx.x;
    int c_reg = 0;
    if (g < NGROUPS) c_reg = sntcs[(g * 8 + wj) * LW + lane];   // prefetch first group

    while (g < NGROUPS) {
        // ================= metadata: one warp per word =================
        int c = c_reg;
        // first-occurrence argmax: maximize value, then minimize index.
        unsigned key = ((unsigned)c << 5) | (unsigned)(31 - lane);
        #pragma unroll
        for (int off = 16; off; off >>= 1) {
            unsigned o = __shfl_xor_sync(0xffffffffu, key, off);
            key = key > o ? key : o;
        }
        int p  = 31 - (int)(key & 31u);          // argmax (first max)
        int wl = p - 1; if (wl < 0) wl = 0;      // relu(argmax - 1)
        int ends = __shfl_sync(0xffffffffu, c, wl);   // gather BEFORE scatter
        int s = (lane == wl) ? 0 : c;            // scatter 0 at wl
        if (lane == 31) s = ends;                // then overwrite last with ends
        sChars[wj * 32 + lane] = (unsigned char)s;

        int gnext = g + NBLK;
        if (gnext < NGROUPS)                     // prefetch next group's chars
            c_reg = sntcs[(gnext * 8 + wj) * LW + lane];

        __syncthreads();

        // ================= gather + write: all 256 threads, 8 words ====
        const int e = tid;                       // dim owned by this thread
        const float* bp = sWT + e;
        #pragma unroll 2
        for (int j = 0; j < 8; j++) {
            const uint32_t* cp = reinterpret_cast<const uint32_t*>(sChars + j * 32);
            uint32_t pk[8];
            #pragma unroll
            for (int i = 0; i < 8; i++) pk[i] = cp[i];   // broadcast LDS

            float first = 0.f, last = 0.f;
            float a0 = 0.f, a1 = 0.f, a2 = 0.f, a3 = 0.f;
            #pragma unroll
            for (int l = 0; l < 32; l++) {
                int ch = (int)((pk[l >> 2] >> ((l & 3) * 8)) & 0xFFu);
                float v = bp[ch * WT_S];         // conflict-free: lanes read e..e+31
                if (l == 0)       first = v;
                else if (l == 31) last  = v;
                else {
                    if      ((l & 3) == 1) a0 += v;
                    else if ((l & 3) == 2) a1 += v;
                    else if ((l & 3) == 3) a2 += v;
                    else                   a3 += v;
                }
            }
            float bow = (a0 + a1) + (a2 + a3);

            int w = g * 8 + j;
            float* o = out + (size_t)w * OUTW;
            o[2 + e]          = first;
            o[2 + E3 + e]     = bow;
            o[2 + 2 * E3 + e] = last;
            if (e < 2) o[e] = 0.f;               // left zero pad (out is poisoned)
        }
        __syncthreads();                         // protect sChars before next group
        g = gnext;
    }
}

extern "C" void kernel_launch(void* const* d_in, const int* in_sizes, int n_in,
                              void* d_out, int out_size)
{
    const int*   sntcs = (const int*)d_in[0];
    const float* W     = (const float*)d_in[1];
    float*       out   = (float*)d_out;

    // Idempotent, host-side, non-stream op: capture-safe.
    cudaFuncSetAttribute(opb_kernel, cudaFuncAttributeMaxDynamicSharedMemorySize, SMEM_BYTES);
    opb_kernel<<<NBLK, BLOCKT, SMEM_BYTES>>>(sntcs, W, out);
}

// round 2
// speedup vs baseline: 1.1258x; 1.1258x over previous
#include <cuda_runtime.h>
#include <cstdint>

#define NWORDS  16384
#define LW      32
#define NC      64
#define E3      256
#define OUTW    770
#define W4S     65          // float4 stride per char row (padded)
#define ROWB    1040u       // bytes per char row = 65 * 16
#define NGROUPS 2048        // NWORDS / 8
#define NBLK    444         // 148 SMs * 3 resident blocks
#define BLOCKT  256

typedef unsigned long long ull;

static constexpr int SMEM_FLOATS = NC * W4S * 4;                    // 16640
static constexpr int SMEM_BYTES  = SMEM_FLOATS * 4 + 8 * LW * 4;    // WT + offsets

__device__ __forceinline__ void lds128(uint32_t addr, ull &a, ull &b) {
    asm("ld.shared.v2.b64 {%0,%1}, [%2];" : "=l"(a), "=l"(b) : "r"(addr));
}
__device__ __forceinline__ ull add2(ull a, ull b) {
    ull r; asm("add.rn.f32x2 %0, %1, %2;" : "=l"(r) : "l"(a), "l"(b)); return r;
}

__global__ __launch_bounds__(BLOCKT) void opb_kernel(
    const int* __restrict__ sntcs, const float* __restrict__ W,
    float* __restrict__ out)
{
    extern __shared__ float smem[];
    float*    sWT   = smem;                                   // [64][65] float4 rows
    uint32_t* sOffs = (uint32_t*)(smem + SMEM_FLOATS);        // [8][32] byte offsets

    const int tid  = threadIdx.x;
    const int lane = tid & 31;
    const int wj   = tid >> 5;     // metadata: warp per word
    const int team = tid >> 6;     // gather: 64-thread team per word
    const int et   = tid & 63;     // float4 index owned by this thread

    // Fill shared WT: sWT4[c][e4] holds dims 4*e4..4*e4+3 of char c.
    for (int idx = tid; idx < E3 * NC; idx += BLOCKT) {
        int e = idx >> 6, c = idx & 63;
        sWT[c * (W4S * 4) + e] = W[idx];
    }

    uint32_t sbase;
    asm("{ .reg .u64 t; cvta.to.shared.u64 t, %1; cvt.u32.u64 %0, t; }"
        : "=r"(sbase) : "l"(smem));
    const uint32_t gbase = sbase + (uint32_t)et * 16u;

    int g = blockIdx.x;
    int c_reg = 0;
    if (g < NGROUPS) c_reg = sntcs[(g * 8 + wj) * LW + lane];   // prefetch

    while (g < NGROUPS) {
        // ---- metadata: one warp per word; first-occurrence argmax ----
        int c = c_reg;
        unsigned key = ((unsigned)c << 5) | (unsigned)(31 - lane);
        #pragma unroll
        for (int off = 16; off; off >>= 1) {
            unsigned o = __shfl_xor_sync(0xffffffffu, key, off);
            key = key > o ? key : o;
        }
        int p  = 31 - (int)(key & 31u);           // argmax, first max wins
        int wl = p - 1; if (wl < 0) wl = 0;       // relu(argmax - 1)
        int ends = __shfl_sync(0xffffffffu, c, wl);  // gather BEFORE scatter
        int s = (lane == wl) ? 0 : c;             // scatter 0 at wl
        if (lane == 31) s = ends;                 // overwrite last with ends
        sOffs[wj * LW + lane] = (uint32_t)s * ROWB;  // precomputed row offset

        int gnext = g + NBLK;
        if (gnext < NGROUPS)
            c_reg = sntcs[(gnext * 8 + wj) * LW + lane];

        __syncthreads();

        // ---- gather: 64 threads per word, 4 dims each, 2 words per thread ----
        #pragma unroll
        for (int jj = 0; jj < 2; jj++) {
            const int j = team * 2 + jj;
            const uint4* op = (const uint4*)(sOffs + j * LW);

            ull f01 = 0, f23 = 0, l01 = 0, l23 = 0;
            ull a01 = 0, a23 = 0, b01 = 0, b23 = 0;

            #pragma unroll
            for (int k = 0; k < 8; k++) {
                uint4 ck = op[k];                  // 4 offsets, broadcast LDS.128
                #pragma unroll
                for (int q = 0; q < 4; q++) {
                    const int l = 4 * k + q;
                    uint32_t off4 = (q == 0) ? ck.x : (q == 1) ? ck.y
                                  : (q == 2) ? ck.z : ck.w;
                    ull v01, v23;
                    lds128(gbase + off4, v01, v23);
                    if (l == 0)            { f01 = v01; f23 = v23; }
                    else if (l == LW - 1)  { l01 = v01; l23 = v23; }
                    else if (l & 1)        { a01 = add2(a01, v01); a23 = add2(a23, v23); }
                    else                   { b01 = add2(b01, v01); b23 = add2(b23, v23); }
                }
            }
            ull s01 = add2(a01, b01), s23 = add2(a23, b23);

            const int w = g * 8 + j;
            float* o = out + (size_t)w * OUTW + 4 * et;
            *(ull*)(o + 2)          = f01;   // first  (base offset 2: 8B aligned)
            *(ull*)(o + 4)          = f23;
            *(ull*)(o + 2 + E3)     = s01;   // bow
            *(ull*)(o + 4 + E3)     = s23;
            *(ull*)(o + 2 + 2*E3)   = l01;   // last
            *(ull*)(o + 4 + 2*E3)   = l23;
            if (et == 0) *(ull*)(out + (size_t)w * OUTW) = 0ull;  // left pad
        }
        __syncthreads();
        g = gnext;
    }
}

extern "C" void kernel_launch(void* const* d_in, const int* in_sizes, int n_in,
                              void* d_out, int out_size)
{
    const int*   sntcs = (const int*)d_in[0];
    const float* W     = (const float*)d_in[1];
    float*       out   = (float*)d_out;

    cudaFuncSetAttribute(opb_kernel, cudaFuncAttributeMaxDynamicSharedMemorySize, SMEM_BYTES);
    opb_kernel<<<NBLK, BLOCKT, SMEM_BYTES>>>(sntcs, W, out);
}